// round 4
// baseline (speedup 1.0000x reference)
#include <cuda_runtime.h>
#include <cstdint>

// LTU_5918464934238: binary-threshold GEMV via TMA-bulk pipelined stream.
// out[i] = (W[i]·x + count(W[i]<0) < 2457.6) ? 0 : 1
//
// W (128 MB) is streamed DRAM->SMEM with cp.async.bulk (UBLKCP) through a
// 5-stage, 16KB-per-stage pipeline per block; compute reads SMEM only.
// grid=296 (2 CTAs/SM), each block handles rows bid, bid+296, ...

#define LTU_THREADS 256
#define LTU_STAGES  5
#define LTU_NINP    4096
#define LTU_VECS    1024                    // float4 per row
#define LTU_ROWB    16384                   // bytes per row
#define LTU_GRID    296

__device__ __forceinline__ uint32_t smem_u32(const void* p) {
    return (uint32_t)__cvta_generic_to_shared(p);
}

__device__ __forceinline__ void mbar_init(uint32_t mb, uint32_t count) {
    asm volatile("mbarrier.init.shared.b64 [%0], %1;" :: "r"(mb), "r"(count));
}

__device__ __forceinline__ void issue_row(uint32_t mb, uint32_t dst,
                                          const float* __restrict__ src) {
    asm volatile("mbarrier.arrive.expect_tx.shared.b64 _, [%0], %1;"
                 :: "r"(mb), "r"((uint32_t)LTU_ROWB) : "memory");
    asm volatile(
        "cp.async.bulk.shared::cta.global.mbarrier::complete_tx::bytes"
        " [%0], [%1], %2, [%3];"
        :: "r"(dst), "l"(src), "r"((uint32_t)LTU_ROWB), "r"(mb) : "memory");
}

__device__ __forceinline__ void wait_parity(uint32_t mb, uint32_t phase) {
    uint32_t done;
    asm volatile(
        "{\n\t.reg .pred p;\n\t"
        "mbarrier.try_wait.parity.acquire.cta.shared::cta.b64 p, [%1], %2;\n\t"
        "selp.b32 %0, 1, 0, p;\n\t}"
        : "=r"(done) : "r"(mb), "r"(phase) : "memory");
    while (!done) {
        asm volatile(
            "{\n\t.reg .pred p;\n\t"
            "mbarrier.try_wait.parity.acquire.cta.shared::cta.b64 p, [%1], %2, 0x989680;\n\t"
            "selp.b32 %0, 1, 0, p;\n\t}"
            : "=r"(done) : "r"(mb), "r"(phase) : "memory");
    }
}

__global__ __launch_bounds__(LTU_THREADS)
void ltu_tma_kernel(const float* __restrict__ x,
                    const float* __restrict__ W,
                    float* __restrict__ out,
                    int rows)
{
    extern __shared__ float4 smem[];
    float4* xs     = smem;                      // [0, 16KB)   : x
    float4* stages = smem + LTU_VECS;           // [16KB, 96KB): 5 x 16KB

    __shared__ uint64_t mbar[LTU_STAGES];
    __shared__ float    wsum[2][LTU_THREADS / 32];

    const int tid  = threadIdx.x;
    const int lane = tid & 31;
    const int warp = tid >> 5;
    const int bid  = blockIdx.x;

    // Stage x (16 KB) once.
    const float4* xv = reinterpret_cast<const float4*>(x);
    for (int i = tid; i < LTU_VECS; i += LTU_THREADS)
        xs[i] = xv[i];

    if (tid == 0) {
        #pragma unroll
        for (int s = 0; s < LTU_STAGES; s++)
            mbar_init(smem_u32(&mbar[s]), 1);
    }
    __syncthreads();
    asm volatile("fence.proxy.async.shared::cta;" ::: "memory");

    // Local row count: rows bid, bid+GRID, ...
    const int nloc = (rows > bid) ? (rows - 1 - bid) / LTU_GRID + 1 : 0;

    // Prologue: fill the pipeline.
    if (tid == 0) {
        #pragma unroll
        for (int s = 0; s < LTU_STAGES; s++) {
            if (s < nloc) {
                const int row = bid + s * LTU_GRID;
                issue_row(smem_u32(&mbar[s]),
                          smem_u32(stages + s * LTU_VECS),
                          W + (size_t)row * LTU_NINP);
            }
        }
    }

    for (int j = 0; j < nloc; j++) {
        const int      s     = j % LTU_STAGES;
        const uint32_t phase = (uint32_t)((j / LTU_STAGES) & 1);
        const uint32_t mb    = smem_u32(&mbar[s]);

        wait_parity(mb, phase);

        const float4* __restrict__ buf = stages + s * LTU_VECS;
        const float4 w0 = buf[tid];
        const float4 w1 = buf[tid + 256];
        const float4 w2 = buf[tid + 512];
        const float4 w3 = buf[tid + 768];
        const float4 v0 = xs[tid];
        const float4 v1 = xs[tid + 256];
        const float4 v2 = xs[tid + 512];
        const float4 v3 = xs[tid + 768];

        float a0 = 0.f, a1 = 0.f, a2 = 0.f, a3 = 0.f;
        a0 = fmaf(w0.x, v0.x, a0); a1 = fmaf(w0.y, v0.y, a1);
        a2 = fmaf(w0.z, v0.z, a2); a3 = fmaf(w0.w, v0.w, a3);
        a0 = fmaf(w1.x, v1.x, a0); a1 = fmaf(w1.y, v1.y, a1);
        a2 = fmaf(w1.z, v1.z, a2); a3 = fmaf(w1.w, v1.w, a3);
        a0 = fmaf(w2.x, v2.x, a0); a1 = fmaf(w2.y, v2.y, a1);
        a2 = fmaf(w2.z, v2.z, a2); a3 = fmaf(w2.w, v2.w, a3);
        a0 = fmaf(w3.x, v3.x, a0); a1 = fmaf(w3.y, v3.y, a1);
        a2 = fmaf(w3.z, v3.z, a2); a3 = fmaf(w3.w, v3.w, a3);

        const unsigned c =
            (__float_as_uint(w0.x) >> 31) + (__float_as_uint(w0.y) >> 31) +
            (__float_as_uint(w0.z) >> 31) + (__float_as_uint(w0.w) >> 31) +
            (__float_as_uint(w1.x) >> 31) + (__float_as_uint(w1.y) >> 31) +
            (__float_as_uint(w1.z) >> 31) + (__float_as_uint(w1.w) >> 31) +
            (__float_as_uint(w2.x) >> 31) + (__float_as_uint(w2.y) >> 31) +
            (__float_as_uint(w2.z) >> 31) + (__float_as_uint(w2.w) >> 31) +
            (__float_as_uint(w3.x) >> 31) + (__float_as_uint(w3.y) >> 31) +
            (__float_as_uint(w3.z) >> 31) + (__float_as_uint(w3.w) >> 31);

        float t = (a0 + a1) + (a2 + a3) + (float)c;

        #pragma unroll
        for (int o = 16; o > 0; o >>= 1)
            t += __shfl_xor_sync(0xffffffffu, t, o);
        if (lane == 0) wsum[j & 1][warp] = t;

        __syncthreads();   // all reads of stage s done; wsum visible

        // Reissue this stage for row j+STAGES (buffer free now).
        if (tid == 0 && (j + LTU_STAGES) < nloc) {
            const int row = bid + (j + LTU_STAGES) * LTU_GRID;
            issue_row(mb, smem_u32(stages + s * LTU_VECS),
                      W + (size_t)row * LTU_NINP);
        }

        if (warp == 0) {
            float ssum = (lane < (LTU_THREADS / 32)) ? wsum[j & 1][lane] : 0.f;
            #pragma unroll
            for (int o = (LTU_THREADS / 64); o > 0; o >>= 1)
                ssum += __shfl_xor_sync(0xffffffffu, ssum, o);
            if (lane == 0) {
                const float tau_base = 0.6f * 4096.0f;  // 2457.60009765625
                out[bid + j * LTU_GRID] = (ssum < tau_base) ? 0.0f : 1.0f;
            }
        }
        // Max warp skew is 1 row (per-row barrier above), so wsum[2] ping-pong
        // is race-free without a second barrier.
    }
}

extern "C" void kernel_launch(void* const* d_in, const int* in_sizes, int n_in,
                              void* d_out, int out_size)
{
    const float* x = (const float*)d_in[0];
    const float* W = (const float*)d_in[1];
    if (n_in >= 2 && in_sizes[0] > in_sizes[1]) {
        x = (const float*)d_in[1];
        W = (const float*)d_in[0];
    }
    float* out = (float*)d_out;
    const int rows = out_size;               // 8192

    const int smem_bytes = (1 + LTU_STAGES) * LTU_ROWB;   // 96 KB dynamic
    static bool attr_set = false;
    if (!attr_set) {
        cudaFuncSetAttribute(ltu_tma_kernel,
                             cudaFuncAttributeMaxDynamicSharedMemorySize,
                             smem_bytes);
        attr_set = true;
    }
    ltu_tma_kernel<<<LTU_GRID, LTU_THREADS, smem_bytes>>>(x, W, out, rows);
}